// round 5
// baseline (speedup 1.0000x reference)
#include <cuda_runtime.h>
#include <math.h>

// Shapes (fixed by the problem)
#define B_   2
#define H_   8
#define N_   64
#define TD_  1024          // T*D = 32*32
#define BH_  (B_ * H_)     // 16
#define INV_SCALE_ (1.0f / 32.0f)   // 1/sqrt(T*D)

#define KCH_  64                 // k-elements per chunk
#define NCH_  (TD_ / KCH_)       // 16 chunks
#define SSTR_ 65                 // smem row stride (odd -> conflict-free)

#define PREF_J_ 12               // V rows (per i-row) prefetched to L2 pre-sync

// Partial scores: [chunk][bh][(m*4+n)*256 + tid]  where
// score(row = ty+16m, col = tx+16n), tid = tx*16+ty.   16*16*4096 floats = 4 MB
__device__ float g_part[NCH_ * BH_ * N_ * N_];

// ---------------------------------------------------------------------------
// Kernel A: partial QK^T. grid = NCH_*BH_ = 256 blocks, 256 threads.
// ---------------------------------------------------------------------------
__global__ __launch_bounds__(256, 2)
void qk_part_kernel(const float* __restrict__ Q,
                    const float* __restrict__ K)
{
#if __CUDA_ARCH__ >= 900
    cudaTriggerProgrammaticLaunchCompletion();
#endif

    __shared__ float sQ[N_ * SSTR_];
    __shared__ float sK[N_ * SSTR_];

    const int bx = blockIdx.x;
    const int bh = bx & (BH_ - 1);
    const int c  = bx >> 4;          // chunk index 0..15
    const int tid = threadIdx.x;

#pragma unroll
    for (int it = 0; it < 16; ++it) {
        int idx = tid + 256 * it;
        int row = idx >> 6;          // 0..63
        int col = idx & 63;          // 0..63
        size_t g = (size_t)(bh * N_ + row) * TD_ + c * KCH_ + col;
        sQ[row * SSTR_ + col] = Q[g];
        sK[row * SSTR_ + col] = K[g];
    }
    __syncthreads();

    const int ty = tid & 15;         // row group
    const int tx = tid >> 4;         // col group

    float acc[4][4];
#pragma unroll
    for (int m = 0; m < 4; ++m)
#pragma unroll
        for (int n = 0; n < 4; ++n) acc[m][n] = 0.0f;

#pragma unroll 4
    for (int k = 0; k < KCH_; ++k) {
        float q[4], kk[4];
#pragma unroll
        for (int m = 0; m < 4; ++m) q[m]  = sQ[(ty + 16 * m) * SSTR_ + k];
#pragma unroll
        for (int n = 0; n < 4; ++n) kk[n] = sK[(tx + 16 * n) * SSTR_ + k];
#pragma unroll
        for (int m = 0; m < 4; ++m)
#pragma unroll
            for (int n = 0; n < 4; ++n)
                acc[m][n] += q[m] * kk[n];
    }

    float* dst = g_part + ((size_t)c * BH_ + bh) * (N_ * N_);
#pragma unroll
    for (int m = 0; m < 4; ++m)
#pragma unroll
        for (int n = 0; n < 4; ++n)
            dst[(m * 4 + n) * 256 + tid] = acc[m][n];
}

// ---------------------------------------------------------------------------
// Kernel B: 2 i-rows per CTA. grid = BH*32 = 512 blocks (single wave),
// 256 threads. PDL: prologue + V L2-prefetch overlap kernel A.
// ---------------------------------------------------------------------------
__global__ __launch_bounds__(256, 4)
void attn_v_kernel(const float* __restrict__ V,
                   const int*   __restrict__ mask,
                   float*       __restrict__ out)
{
    const int bx   = blockIdx.x;          // 0 .. BH*32-1
    const int ip   = bx & 31;             // i-pair index
    const int bh   = bx >> 5;
    const int i0   = ip * 2;              // even row
    const int tid  = threadIdx.x;
    const int lane = tid & 31;
    const int warp = tid >> 5;

    __shared__ float s_attn[2][N_];

    // ---- Pre-sync (independent of kernel A's output) ----
    const float4* V0 = reinterpret_cast<const float4*>(V) +
                       ((size_t)bh * N_ * N_ + i0) * (TD_ / 4) + tid;
    const float4* V1 = V0 + (TD_ / 4);    // row i0+1 is adjacent
    const size_t jstride = (size_t)N_ * (TD_ / 4);

    // Prefetch first PREF_J_ V rows (both i-rows) into L2 while A runs.
#pragma unroll
    for (int j = 0; j < PREF_J_; ++j) {
        asm volatile("prefetch.global.L2 [%0];" :: "l"(V0 + (size_t)j * jstride));
        asm volatile("prefetch.global.L2 [%0];" :: "l"(V1 + (size_t)j * jstride));
    }

    // Warp 0 handles row i0, warp 1 handles row i0+1: pre-load masks + idx
    int m0 = 1, m1 = 1;
    int idx0 = 0, idx1 = 0;
    int myrow = i0 + warp;                // valid for warp 0/1
    if (warp < 2) {
        const size_t roff = ((size_t)bh * N_ + myrow) * N_;
        m0 = mask[roff + lane];
        m1 = mask[roff + lane + 32];
        const int mq = myrow >> 4;
        const int ty = myrow & 15;
        idx0 = ((mq * 4 + (lane >> 4)) * 256) + ((lane & 15) * 16 + ty);
        idx1 = ((mq * 4 + ((lane + 32) >> 4)) * 256) + (((lane + 32) & 15) * 16 + ty);
    }

    // ---- Wait for kernel A's g_part ----
#if __CUDA_ARCH__ >= 900
    cudaGridDependencySynchronize();
#endif

    if (warp < 2) {
        const float* base = g_part + (size_t)bh * (N_ * N_);
        float v0 = 0.0f, v1 = 0.0f;
#pragma unroll
        for (int cch = 0; cch < NCH_; ++cch) {
            const float* p = base + (size_t)cch * (BH_ * N_ * N_);
            v0 += p[idx0];
            v1 += p[idx1];
        }
        v0 *= INV_SCALE_;
        v1 *= INV_SCALE_;

        if (m0 == 0) v0 = -INFINITY;
        if (m1 == 0) v1 = -INFINITY;

        float mx = fmaxf(v0, v1);
#pragma unroll
        for (int o = 16; o > 0; o >>= 1) mx = fmaxf(mx, __shfl_xor_sync(0xffffffffu, mx, o));
        float e0 = __expf(v0 - mx);
        float e1 = __expf(v1 - mx);
        float s = e0 + e1;
#pragma unroll
        for (int o = 16; o > 0; o >>= 1) s += __shfl_xor_sync(0xffffffffu, s, o);
        float inv = 1.0f / s;
        s_attn[warp][lane]      = e0 * inv;
        s_attn[warp][lane + 32] = e1 * inv;
    }
    __syncthreads();

    // ---- Streaming contraction for both rows ----
    float4 acc0 = make_float4(0.f, 0.f, 0.f, 0.f);
    float4 acc1 = make_float4(0.f, 0.f, 0.f, 0.f);

#pragma unroll
    for (int j0 = 0; j0 < N_; j0 += 4) {
        float4 a[4], b[4];
#pragma unroll
        for (int jj = 0; jj < 4; ++jj) {
            a[jj] = __ldcs(&V0[(size_t)(j0 + jj) * jstride]);
            b[jj] = __ldcs(&V1[(size_t)(j0 + jj) * jstride]);
        }
#pragma unroll
        for (int jj = 0; jj < 4; ++jj) {
            float w0 = s_attn[0][j0 + jj];
            float w1 = s_attn[1][j0 + jj];
            acc0.x += w0 * a[jj].x;  acc0.y += w0 * a[jj].y;
            acc0.z += w0 * a[jj].z;  acc0.w += w0 * a[jj].w;
            acc1.x += w1 * b[jj].x;  acc1.y += w1 * b[jj].y;
            acc1.z += w1 * b[jj].z;  acc1.w += w1 * b[jj].w;
        }
    }

    float4* O0 = reinterpret_cast<float4*>(out + (size_t)(bh * N_ + i0) * TD_);
    O0[tid]            = acc0;
    O0[tid + TD_ / 4]  = acc1;
}

extern "C" void kernel_launch(void* const* d_in, const int* in_sizes, int n_in,
                              void* d_out, int out_size)
{
    const float* Q    = (const float*)d_in[0];
    const float* K    = (const float*)d_in[1];
    const float* V    = (const float*)d_in[2];
    const int*   mask = (const int*)d_in[3];
    float*       out  = (float*)d_out;

    // Kernel A: normal launch
    qk_part_kernel<<<NCH_ * BH_, 256>>>(Q, K);

    // Kernel B: programmatic dependent launch (overlaps prologue with A)
    cudaLaunchConfig_t cfg = {};
    cfg.gridDim  = dim3(BH_ * 32);
    cfg.blockDim = dim3(256);
    cfg.dynamicSmemBytes = 0;
    cudaLaunchAttribute attrs[1];
    attrs[0].id = cudaLaunchAttributeProgrammaticStreamSerialization;
    attrs[0].val.programmaticStreamSerializationAllowed = 1;
    cfg.attrs = attrs;
    cfg.numAttrs = 1;
    cudaLaunchKernelEx(&cfg, attn_v_kernel, V, mask, out);
}

// round 6
// speedup vs baseline: 1.1588x; 1.1588x over previous
#include <cuda_runtime.h>
#include <math.h>

// Shapes (fixed by the problem)
#define B_   2
#define H_   8
#define N_   64
#define TD_  1024          // T*D = 32*32
#define BH_  (B_ * H_)     // 16
#define INV_SCALE_ (1.0f / 32.0f)   // 1/sqrt(T*D)

#define KCH_  64                 // k-elements per chunk
#define NCH_  (TD_ / KCH_)       // 16 chunks
#define SSTR_ 72                 // smem row stride (floats): 4-aligned, 18*ty%32 all-distinct

#define PREF_J_ 16               // V rows prefetched to L2 pre-sync in kernel B

// Partial scores: [chunk][bh][(m*4+n)*256 + tid]  where
// score(row = ty+16m, col = tx+16n), tid = tx*16+ty.   16*16*4096 floats = 4 MB
__device__ float g_part[NCH_ * BH_ * N_ * N_];

// ---------------------------------------------------------------------------
// Kernel A: partial QK^T. grid = NCH_*BH_ = 256 blocks, 256 threads.
// 4x4 register blocking, float4 smem traffic throughout.
// ---------------------------------------------------------------------------
__global__ __launch_bounds__(256, 2)
void qk_part_kernel(const float* __restrict__ Q,
                    const float* __restrict__ K)
{
#if __CUDA_ARCH__ >= 900
    cudaTriggerProgrammaticLaunchCompletion();
#endif

    __shared__ float sQ[N_ * SSTR_];
    __shared__ float sK[N_ * SSTR_];

    const int bx = blockIdx.x;
    const int bh = bx & (BH_ - 1);
    const int c  = bx >> 4;          // chunk index 0..15
    const int tid = threadIdx.x;

    // Fill: 4096 floats per tile = 4 float4 per thread, coalesced.
#pragma unroll
    for (int it = 0; it < 4; ++it) {
        int idx  = tid + 256 * it;       // float4 index 0..1023
        int row  = idx >> 4;             // 0..63
        int col4 = (idx & 15) * 4;       // 0..60
        size_t g = (size_t)(bh * N_ + row) * TD_ + c * KCH_ + col4;
        float4 q = *reinterpret_cast<const float4*>(Q + g);
        float4 k = *reinterpret_cast<const float4*>(K + g);
        *reinterpret_cast<float4*>(&sQ[row * SSTR_ + col4]) = q;
        *reinterpret_cast<float4*>(&sK[row * SSTR_ + col4]) = k;
    }
    __syncthreads();

    const int ty = tid & 15;         // row group
    const int tx = tid >> 4;         // col group

    float acc[4][4];
#pragma unroll
    for (int m = 0; m < 4; ++m)
#pragma unroll
        for (int n = 0; n < 4; ++n) acc[m][n] = 0.0f;

#pragma unroll 4
    for (int k4 = 0; k4 < KCH_ / 4; ++k4) {
        float4 q[4], kk[4];
#pragma unroll
        for (int m = 0; m < 4; ++m)
            q[m]  = *reinterpret_cast<const float4*>(&sQ[(ty + 16 * m) * SSTR_ + 4 * k4]);
#pragma unroll
        for (int n = 0; n < 4; ++n)
            kk[n] = *reinterpret_cast<const float4*>(&sK[(tx + 16 * n) * SSTR_ + 4 * k4]);
#pragma unroll
        for (int m = 0; m < 4; ++m)
#pragma unroll
            for (int n = 0; n < 4; ++n)
                acc[m][n] += q[m].x * kk[n].x + q[m].y * kk[n].y
                           + q[m].z * kk[n].z + q[m].w * kk[n].w;
    }

    // Coalesced store: layout [c][bh][(m*4+n)*256 + tid]
    float* dst = g_part + ((size_t)c * BH_ + bh) * (N_ * N_);
#pragma unroll
    for (int m = 0; m < 4; ++m)
#pragma unroll
        for (int n = 0; n < 4; ++n)
            dst[(m * 4 + n) * 256 + tid] = acc[m][n];
}

// ---------------------------------------------------------------------------
// Kernel B (R4 winner, unchanged): per-(bh,i) softmax + streaming V pass.
// grid = BH*N = 1024 blocks, 256 threads. PDL overlaps prologue with A.
// ---------------------------------------------------------------------------
__global__ __launch_bounds__(256, 4)
void attn_v_kernel(const float* __restrict__ V,
                   const int*   __restrict__ mask,
                   float*       __restrict__ out)
{
    const int bx   = blockIdx.x;          // 0 .. BH*N-1
    const int i    = bx % N_;
    const int bh   = bx / N_;
    const int tid  = threadIdx.x;
    const int lane = tid & 31;
    const int warp = tid >> 5;

    __shared__ float s_attn[N_];

    // ---- Pre-sync (independent of kernel A's output) ----
    const float4* Vbase = reinterpret_cast<const float4*>(V) +
                          ((size_t)bh * N_ * N_ + i) * (TD_ / 4) + tid;
    const size_t jstride = (size_t)N_ * (TD_ / 4);   // float4 stride between j's

    // Prefetch the first PREF_J_ V rows into L2 while A still runs.
#pragma unroll
    for (int j = 0; j < PREF_J_; ++j)
        asm volatile("prefetch.global.L2 [%0];" :: "l"(Vbase + (size_t)j * jstride));

    // Mask loads (input, not produced by A)
    int m0 = 1, m1 = 1;
    int idx0 = 0, idx1 = 0;
    if (warp == 0) {
        const size_t roff = ((size_t)bh * N_ + i) * N_;
        m0 = mask[roff + lane];
        m1 = mask[roff + lane + 32];
        const int m  = i >> 4;
        const int ty = i & 15;
        int j0 = lane, j1 = lane + 32;
        idx0 = ((m * 4 + (j0 >> 4)) * 256) + ((j0 & 15) * 16 + ty);
        idx1 = ((m * 4 + (j1 >> 4)) * 256) + ((j1 & 15) * 16 + ty);
    }

    // ---- Wait for kernel A's g_part to be visible ----
#if __CUDA_ARCH__ >= 900
    cudaGridDependencySynchronize();
#endif

    // warp 0: gather partial scores, sum, mask, softmax
    if (warp == 0) {
        const float* base = g_part + (size_t)bh * (N_ * N_);
        float v0 = 0.0f, v1 = 0.0f;
#pragma unroll
        for (int cch = 0; cch < NCH_; ++cch) {
            const float* p = base + (size_t)cch * (BH_ * N_ * N_);
            v0 += p[idx0];
            v1 += p[idx1];
        }
        v0 *= INV_SCALE_;
        v1 *= INV_SCALE_;

        if (m0 == 0) v0 = -INFINITY;
        if (m1 == 0) v1 = -INFINITY;

        float mx = fmaxf(v0, v1);
#pragma unroll
        for (int o = 16; o > 0; o >>= 1) mx = fmaxf(mx, __shfl_xor_sync(0xffffffffu, mx, o));
        float e0 = __expf(v0 - mx);
        float e1 = __expf(v1 - mx);
        float s = e0 + e1;
#pragma unroll
        for (int o = 16; o > 0; o >>= 1) s += __shfl_xor_sync(0xffffffffu, s, o);
        float inv = 1.0f / s;
        s_attn[lane]      = e0 * inv;
        s_attn[lane + 32] = e1 * inv;
    }
    __syncthreads();

    // streaming contraction: out[tf] = sum_j attn[j] * V[bh, j, i, tf]
    float4 acc = make_float4(0.f, 0.f, 0.f, 0.f);

#pragma unroll
    for (int j0 = 0; j0 < N_; j0 += 8) {
        float4 v[8];
#pragma unroll
        for (int jj = 0; jj < 8; ++jj)
            v[jj] = __ldcs(&Vbase[(size_t)(j0 + jj) * jstride]);
#pragma unroll
        for (int jj = 0; jj < 8; ++jj) {
            float a = s_attn[j0 + jj];
            acc.x += a * v[jj].x;
            acc.y += a * v[jj].y;
            acc.z += a * v[jj].z;
            acc.w += a * v[jj].w;
        }
    }

    float4* Orow = reinterpret_cast<float4*>(out + (size_t)(bh * N_ + i) * TD_);
    Orow[tid] = acc;
}

extern "C" void kernel_launch(void* const* d_in, const int* in_sizes, int n_in,
                              void* d_out, int out_size)
{
    const float* Q    = (const float*)d_in[0];
    const float* K    = (const float*)d_in[1];
    const float* V    = (const float*)d_in[2];
    const int*   mask = (const int*)d_in[3];
    float*       out  = (float*)d_out;

    // Kernel A: normal launch
    qk_part_kernel<<<NCH_ * BH_, 256>>>(Q, K);

    // Kernel B: programmatic dependent launch (overlaps prologue with A)
    cudaLaunchConfig_t cfg = {};
    cfg.gridDim  = dim3(BH_ * N_);
    cfg.blockDim = dim3(256);
    cfg.dynamicSmemBytes = 0;
    cudaLaunchAttribute attrs[1];
    attrs[0].id = cudaLaunchAttributeProgrammaticStreamSerialization;
    attrs[0].val.programmaticStreamSerializationAllowed = 1;
    cfg.attrs = attrs;
    cfg.numAttrs = 1;
    cudaLaunchKernelEx(&cfg, attn_v_kernel, V, mask, out);
}

// round 7
// speedup vs baseline: 1.2034x; 1.0384x over previous
#include <cuda_runtime.h>
#include <math.h>

// Shapes (fixed by the problem)
#define B_   2
#define H_   8
#define N_   64
#define TD_  1024          // T*D = 32*32
#define BH_  (B_ * H_)     // 16
#define INV_SCALE_ (1.0f / 32.0f)   // 1/sqrt(T*D)

#define KCH_  64                 // k-elements per chunk
#define NCH_  (TD_ / KCH_)       // 16 chunks
#define SSTR_ 65                 // smem row stride (odd -> conflict-free)

#define PREF_J_ 16               // V rows prefetched to L2 pre-sync in kernel B

// Partial scores, row-major: [chunk][bh][i][j].  16*16*64*64 floats = 4 MB
__device__ float g_part[NCH_ * BH_ * N_ * N_];

// ---------------------------------------------------------------------------
// Kernel A: partial QK^T. grid = NCH_*BH_ = 256 blocks, 256 threads.
// 4x4 register blocking (scalar smem reads, R4 core), then restaged through
// smem so the global store of the 64x64 tile is fully coalesced row-major.
// ---------------------------------------------------------------------------
__global__ __launch_bounds__(256, 2)
void qk_part_kernel(const float* __restrict__ Q,
                    const float* __restrict__ K)
{
#if __CUDA_ARCH__ >= 900
    cudaTriggerProgrammaticLaunchCompletion();
#endif

    __shared__ float sQ[N_ * SSTR_];
    __shared__ float sK[N_ * SSTR_];

    const int bx = blockIdx.x;
    const int bh = bx & (BH_ - 1);
    const int c  = bx >> 4;          // chunk index 0..15
    const int tid = threadIdx.x;

    // Fill: 4096 floats per tile, 16 per thread, coalesced.
#pragma unroll
    for (int it = 0; it < 16; ++it) {
        int idx = tid + 256 * it;
        int row = idx >> 6;          // 0..63
        int col = idx & 63;          // 0..63
        size_t g = (size_t)(bh * N_ + row) * TD_ + c * KCH_ + col;
        sQ[row * SSTR_ + col] = Q[g];
        sK[row * SSTR_ + col] = K[g];
    }
    __syncthreads();

    const int ty = tid & 15;         // row group
    const int tx = tid >> 4;         // col group

    float acc[4][4];
#pragma unroll
    for (int m = 0; m < 4; ++m)
#pragma unroll
        for (int n = 0; n < 4; ++n) acc[m][n] = 0.0f;

#pragma unroll 4
    for (int k = 0; k < KCH_; ++k) {
        float q[4], kk[4];
#pragma unroll
        for (int m = 0; m < 4; ++m) q[m]  = sQ[(ty + 16 * m) * SSTR_ + k];
#pragma unroll
        for (int n = 0; n < 4; ++n) kk[n] = sK[(tx + 16 * n) * SSTR_ + k];
#pragma unroll
        for (int m = 0; m < 4; ++m)
#pragma unroll
            for (int n = 0; n < 4; ++n)
                acc[m][n] += q[m] * kk[n];
    }

    // Restage through smem (reuse sQ) so the global store is coalesced.
    __syncthreads();                 // everyone done reading sQ/sK
#pragma unroll
    for (int m = 0; m < 4; ++m)
#pragma unroll
        for (int n = 0; n < 4; ++n)
            sQ[(ty + 16 * m) * SSTR_ + (tx + 16 * n)] = acc[m][n];
    __syncthreads();

    // Coalesced row-major store: g_part[c][bh][row][col]
    float* dst = g_part + ((size_t)c * BH_ + bh) * (N_ * N_);
#pragma unroll
    for (int it = 0; it < 16; ++it) {
        int idx = tid + 256 * it;
        int row = idx >> 6;
        int col = idx & 63;
        dst[idx] = sQ[row * SSTR_ + col];
    }
}

// ---------------------------------------------------------------------------
// Kernel B: per-(bh,i) softmax + streaming V pass.
// grid = BH*N = 1024 blocks, 256 threads. PDL overlaps prologue with A.
// Score gather is now fully coalesced (row-major g_part).
// ---------------------------------------------------------------------------
__global__ __launch_bounds__(256, 4)
void attn_v_kernel(const float* __restrict__ V,
                   const int*   __restrict__ mask,
                   float*       __restrict__ out)
{
    const int bx   = blockIdx.x;          // 0 .. BH*N-1
    const int i    = bx % N_;
    const int bh   = bx / N_;
    const int tid  = threadIdx.x;
    const int lane = tid & 31;
    const int warp = tid >> 5;

    __shared__ float s_attn[N_];

    // ---- Pre-sync (independent of kernel A's output) ----
    const float4* Vbase = reinterpret_cast<const float4*>(V) +
                          ((size_t)bh * N_ * N_ + i) * (TD_ / 4) + tid;
    const size_t jstride = (size_t)N_ * (TD_ / 4);   // float4 stride between j's

    // Prefetch the first PREF_J_ V rows into L2 while A still runs.
#pragma unroll
    for (int j = 0; j < PREF_J_; ++j)
        asm volatile("prefetch.global.L2 [%0];" :: "l"(Vbase + (size_t)j * jstride));

    // Mask loads (input, not produced by A)
    int m0 = 1, m1 = 1;
    if (warp == 0) {
        const size_t roff = ((size_t)bh * N_ + i) * N_;
        m0 = mask[roff + lane];
        m1 = mask[roff + lane + 32];
    }

    // ---- Wait for kernel A's g_part to be visible ----
#if __CUDA_ARCH__ >= 900
    cudaGridDependencySynchronize();
#endif

    // warp 0: gather partial scores (coalesced), sum, mask, softmax
    if (warp == 0) {
        const float* base = g_part + ((size_t)bh * N_ + i) * N_;
        float v0 = 0.0f, v1 = 0.0f;
#pragma unroll
        for (int cch = 0; cch < NCH_; ++cch) {
            const float* p = base + (size_t)cch * (BH_ * N_ * N_);
            v0 += p[lane];
            v1 += p[lane + 32];
        }
        v0 *= INV_SCALE_;
        v1 *= INV_SCALE_;

        if (m0 == 0) v0 = -INFINITY;
        if (m1 == 0) v1 = -INFINITY;

        float mx = fmaxf(v0, v1);
#pragma unroll
        for (int o = 16; o > 0; o >>= 1) mx = fmaxf(mx, __shfl_xor_sync(0xffffffffu, mx, o));
        float e0 = __expf(v0 - mx);
        float e1 = __expf(v1 - mx);
        float s = e0 + e1;
#pragma unroll
        for (int o = 16; o > 0; o >>= 1) s += __shfl_xor_sync(0xffffffffu, s, o);
        float inv = 1.0f / s;
        s_attn[lane]      = e0 * inv;
        s_attn[lane + 32] = e1 * inv;
    }
    __syncthreads();

    // streaming contraction: out[tf] = sum_j attn[j] * V[bh, j, i, tf]
    float4 acc = make_float4(0.f, 0.f, 0.f, 0.f);

#pragma unroll
    for (int j0 = 0; j0 < N_; j0 += 8) {
        float4 v[8];
#pragma unroll
        for (int jj = 0; jj < 8; ++jj)
            v[jj] = __ldcs(&Vbase[(size_t)(j0 + jj) * jstride]);
#pragma unroll
        for (int jj = 0; jj < 8; ++jj) {
            float a = s_attn[j0 + jj];
            acc.x += a * v[jj].x;
            acc.y += a * v[jj].y;
            acc.z += a * v[jj].z;
            acc.w += a * v[jj].w;
        }
    }

    float4* Orow = reinterpret_cast<float4*>(out + (size_t)(bh * N_ + i) * TD_);
    __stcs(&Orow[tid], acc);
}

extern "C" void kernel_launch(void* const* d_in, const int* in_sizes, int n_in,
                              void* d_out, int out_size)
{
    const float* Q    = (const float*)d_in[0];
    const float* K    = (const float*)d_in[1];
    const float* V    = (const float*)d_in[2];
    const int*   mask = (const int*)d_in[3];
    float*       out  = (float*)d_out;

    // Kernel A: normal launch
    qk_part_kernel<<<NCH_ * BH_, 256>>>(Q, K);

    // Kernel B: programmatic dependent launch (overlaps prologue with A)
    cudaLaunchConfig_t cfg = {};
    cfg.gridDim  = dim3(BH_ * N_);
    cfg.blockDim = dim3(256);
    cfg.dynamicSmemBytes = 0;
    cudaLaunchAttribute attrs[1];
    attrs[0].id = cudaLaunchAttributeProgrammaticStreamSerialization;
    attrs[0].val.programmaticStreamSerializationAllowed = 1;
    cfg.attrs = attrs;
    cfg.numAttrs = 1;
    cudaLaunchKernelEx(&cfg, attn_v_kernel, V, mask, out);
}